// round 5
// baseline (speedup 1.0000x reference)
#include <cuda_runtime.h>

#define N_NODES 25000
#define N_EDGES 100000
#define NODE_IN 8
#define HID 32

// Scratch (device globals — allocation is forbidden). Accessed only from device code.
__device__ float g_h1[N_NODES * HID];
__device__ float g_h2[N_NODES * HID];
__device__ float g_agg[N_NODES * HID];
__device__ float g_cnt[N_NODES];
__device__ float g_inv[N_NODES];
__device__ int   g_src[N_EDGES];
__device__ int   g_dst[N_EDGES];
__device__ int   g_bad64;

// ---------------------------------------------------------------------------
// Index ingestion: detect int64 vs int32 edge_index, convert to int, clamp.
// ---------------------------------------------------------------------------
__global__ void idx_zero_kernel() {
    if (blockIdx.x == 0 && threadIdx.x == 0) g_bad64 = 0;
}

// Read the FIRST N_EDGES words as int64. This spans exactly the whole buffer
// if it is int32 (2*N_EDGES*4 bytes) and the src half if it is int64 — no OOB
// either way. int64 data -> all values in [0,N_NODES) -> bad stays 0.
// int32 data -> pairs packed into one word -> out of range almost everywhere.
__global__ void idx_detect_kernel(const void* __restrict__ ei) {
    int e = blockIdx.x * blockDim.x + threadIdx.x;
    if (e < N_EDGES) {
        long long v = ((const long long*)ei)[e];
        if (v < 0 || v >= N_NODES) atomicAdd(&g_bad64, 1);
    }
}

__global__ void idx_convert_kernel(const void* __restrict__ ei) {
    int e = blockIdx.x * blockDim.x + threadIdx.x;
    if (e >= N_EDGES) return;
    const bool is64 = (g_bad64 == 0);
    long long s, d;
    if (is64) {
        s = ((const long long*)ei)[e];
        d = ((const long long*)ei)[N_EDGES + e];
    } else {
        s = ((const int*)ei)[e];
        d = ((const int*)ei)[N_EDGES + e];
    }
    int si = (int)s, di = (int)d;
    si = si < 0 ? 0 : (si >= N_NODES ? N_NODES - 1 : si);
    di = di < 0 ? 0 : (di >= N_NODES ? N_NODES - 1 : di);
    g_src[e] = si;
    g_dst[e] = di;
}

// ---------------------------------------------------------------------------
// Zero agg (+ cnt when requested)
// ---------------------------------------------------------------------------
__global__ void zero_kernel(int also_cnt) {
    int i = blockIdx.x * blockDim.x + threadIdx.x;
    if (i < N_NODES * HID) g_agg[i] = 0.0f;
    if (also_cnt && i < N_NODES) g_cnt[i] = 0.0f;
}

// ---------------------------------------------------------------------------
// In-degree counts (one thread per edge). Runs once; dst is layer-invariant.
// ---------------------------------------------------------------------------
__global__ void degree_kernel() {
    int e = blockIdx.x * blockDim.x + threadIdx.x;
    if (e < N_EDGES) atomicAdd(&g_cnt[g_dst[e]], 1.0f);
}

// ---------------------------------------------------------------------------
// Edge kernel: one warp per edge (grid-stride).
// lane o computes msg[o] = sum_i h[src,i] * relu( ea . W[:, i*32+o] + b )
// Weights resident in static smem, transposed so the 4 edge-attr rows of one
// column form a float4 (one LDS.128 feeds 4 FMAs). SEL picks the feature
// buffer at compile time: 0 -> param x, 1 -> g_h1, 2 -> g_h2.
// ---------------------------------------------------------------------------
template <int IN, int SEL>
__global__ void __launch_bounds__(256)
edge_kernel(const float* __restrict__ x,
            const float* __restrict__ ea,
            const float* __restrict__ w_mlp,  // [4, IN*HID] row-major
            const float* __restrict__ b_mlp)  // [IN*HID]
{
    constexpr int COLS = IN * HID;
    __shared__ float4 ws[COLS];
    __shared__ float  bs[COLS];

    for (int c = threadIdx.x; c < COLS; c += blockDim.x) {
        ws[c] = make_float4(w_mlp[c], w_mlp[COLS + c],
                            w_mlp[2 * COLS + c], w_mlp[3 * COLS + c]);
        bs[c] = b_mlp[c];
    }
    __syncthreads();

    const int lane   = (int)(threadIdx.x & 31u);
    const int warp   = (int)((blockIdx.x * blockDim.x + threadIdx.x) >> 5);
    const int nwarps = (int)((gridDim.x * blockDim.x) >> 5);

    for (int e = warp; e < N_EDGES; e += nwarps) {
        const int src = g_src[e];
        const int dst = g_dst[e];

        // each lane holds one source feature (IN is a power of two)
        float xv;
        if (SEL == 0)      xv = x[src * IN + (lane & (IN - 1))];
        else if (SEL == 1) xv = g_h1[src * IN + (lane & (IN - 1))];
        else               xv = g_h2[src * IN + (lane & (IN - 1))];

        const float4 eav = *(const float4*)(ea + 4 * e);

        float msg = 0.0f;
        #pragma unroll
        for (int i = 0; i < IN; ++i) {
            float xi = __shfl_sync(0xffffffffu, xv, i);
            int c = i * HID + lane;
            float4 w = ws[c];
            float a = bs[c];
            a = fmaf(eav.x, w.x, a);
            a = fmaf(eav.y, w.y, a);
            a = fmaf(eav.z, w.z, a);
            a = fmaf(eav.w, w.w, a);
            msg = fmaf(xi, fmaxf(a, 0.0f), msg);
        }
        atomicAdd(&g_agg[dst * HID + lane], msg);
    }
}

// ---------------------------------------------------------------------------
// Node update: h_out = relu(agg/max(cnt,1) + h_in @ root + bias)
// One warp per node; lane = output feature.
// SEL input: 0 -> x param, 1 -> g_h1. OUTSEL: 1 -> g_h1, 2 -> g_h2.
// ---------------------------------------------------------------------------
template <int IN, int SEL, int OUTSEL, bool FIRST>
__global__ void __launch_bounds__(256)
node_kernel(const float* __restrict__ x,
            const float* __restrict__ root,   // [IN, HID]
            const float* __restrict__ bias)   // [HID]
{
    __shared__ float rs[IN * HID];
    for (int i = threadIdx.x; i < IN * HID; i += blockDim.x) rs[i] = root[i];
    __syncthreads();

    const int lane = (int)(threadIdx.x & 31u);
    const int n    = (int)((blockIdx.x * blockDim.x + threadIdx.x) >> 5);
    if (n >= N_NODES) return;

    float inv;
    if (FIRST) {
        float c = g_cnt[n];
        inv = 1.0f / fmaxf(c, 1.0f);
        if (lane == 0) g_inv[n] = inv;
    } else {
        inv = g_inv[n];
    }

    float hv;
    if (SEL == 0) hv = x[n * IN + (lane & (IN - 1))];
    else          hv = g_h1[n * IN + (lane & (IN - 1))];

    float acc = g_agg[n * HID + lane] * inv + bias[lane];
    #pragma unroll
    for (int i = 0; i < IN; ++i)
        acc = fmaf(__shfl_sync(0xffffffffu, hv, i), rs[i * HID + lane], acc);

    float r = fmaxf(acc, 0.0f);
    if (OUTSEL == 1) g_h1[n * HID + lane] = r;
    else             g_h2[n * HID + lane] = r;
}

// ---------------------------------------------------------------------------
// Layer-3 node update fused with output head:
// h3 = relu(agg/cnt + h2 @ root3 + bias3)
// t  = relu(h3 @ w_out1 + b_out1); out = t @ w_out2 + b_out2
// ---------------------------------------------------------------------------
__global__ void __launch_bounds__(256)
node3_kernel(const float* __restrict__ root,    // [HID, HID]
             const float* __restrict__ bias,    // [HID]
             const float* __restrict__ w_out1,  // [HID, HID]
             const float* __restrict__ b_out1,  // [HID]
             const float* __restrict__ w_out2,  // [HID, 1]
             const float* __restrict__ b_out2,  // [1]
             float* __restrict__ out)
{
    __shared__ float rs[HID * HID];
    __shared__ float wo[HID * HID];
    for (int i = threadIdx.x; i < HID * HID; i += blockDim.x) {
        rs[i] = root[i];
        wo[i] = w_out1[i];
    }
    __syncthreads();

    const int lane = (int)(threadIdx.x & 31u);
    const int n    = (int)((blockIdx.x * blockDim.x + threadIdx.x) >> 5);
    if (n >= N_NODES) return;

    float inv = g_inv[n];
    float acc = g_agg[n * HID + lane] * inv + bias[lane];
    float hv  = g_h2[n * HID + lane];
    #pragma unroll
    for (int i = 0; i < HID; ++i)
        acc = fmaf(__shfl_sync(0xffffffffu, hv, i), rs[i * HID + lane], acc);
    float h3 = fmaxf(acc, 0.0f);

    // head layer 1
    float acc2 = b_out1[lane];
    #pragma unroll
    for (int o = 0; o < HID; ++o)
        acc2 = fmaf(__shfl_sync(0xffffffffu, h3, o), wo[o * HID + lane], acc2);

    // head layer 2 (32 -> 1): warp reduction
    float t = fmaxf(acc2, 0.0f) * w_out2[lane];
    #pragma unroll
    for (int off = 16; off; off >>= 1)
        t += __shfl_xor_sync(0xffffffffu, t, off);

    if (lane == 0) out[n] = t + b_out2[0];
}

// ---------------------------------------------------------------------------
extern "C" void kernel_launch(void* const* d_in, const int* in_sizes, int n_in,
                              void* d_out, int out_size)
{
    (void)in_sizes; (void)n_in; (void)out_size;

    const float* x      = (const float*)d_in[0];
    const void*  ei     = d_in[1];                 // dtype detected on device
    const float* ea     = (const float*)d_in[2];
    const float* w_mlp1 = (const float*)d_in[3];
    const float* b_mlp1 = (const float*)d_in[4];
    const float* root1  = (const float*)d_in[5];
    const float* bias1  = (const float*)d_in[6];
    const float* w_mlp2 = (const float*)d_in[7];
    const float* b_mlp2 = (const float*)d_in[8];
    const float* root2  = (const float*)d_in[9];
    const float* bias2  = (const float*)d_in[10];
    const float* w_mlp3 = (const float*)d_in[11];
    const float* b_mlp3 = (const float*)d_in[12];
    const float* root3  = (const float*)d_in[13];
    const float* bias3  = (const float*)d_in[14];
    const float* w_out1 = (const float*)d_in[15];
    const float* b_out1 = (const float*)d_in[16];
    const float* w_out2 = (const float*)d_in[17];
    const float* b_out2 = (const float*)d_in[18];
    float*       out    = (float*)d_out;

    const int ZB = (N_NODES * HID + 255) / 256;   // zero-kernel blocks
    const int DB = (N_EDGES + 255) / 256;         // per-edge blocks
    const int NB = (N_NODES * 32 + 255) / 256;    // node blocks (warp per node)
    const int EB = 1184;                          // edge blocks: 8/SM x 148 SM

    // Index ingestion (dtype-agnostic, clamped)
    idx_zero_kernel<<<1, 32>>>();
    idx_detect_kernel<<<DB, 256>>>(ei);
    idx_convert_kernel<<<DB, 256>>>(ei);

    // Layer 1 (IN = 8): x -> g_h1  (plus degree counts)
    zero_kernel<<<ZB, 256>>>(1);
    degree_kernel<<<DB, 256>>>();
    edge_kernel<NODE_IN, 0><<<EB, 256>>>(x, ea, w_mlp1, b_mlp1);
    node_kernel<NODE_IN, 0, 1, true><<<NB, 256>>>(x, root1, bias1);

    // Layer 2 (IN = 32): g_h1 -> g_h2
    zero_kernel<<<ZB, 256>>>(0);
    edge_kernel<HID, 1><<<EB, 256>>>(x, ea, w_mlp2, b_mlp2);
    node_kernel<HID, 1, 2, false><<<NB, 256>>>(x, root2, bias2);

    // Layer 3 (IN = 32) + fused output head: g_h2 -> out
    zero_kernel<<<ZB, 256>>>(0);
    edge_kernel<HID, 2><<<EB, 256>>>(x, ea, w_mlp3, b_mlp3);
    node3_kernel<<<NB, 256>>>(root3, bias3, w_out1, b_out1, w_out2, b_out2, out);
}

// round 6
// speedup vs baseline: 1.0229x; 1.0229x over previous
#include <cuda_runtime.h>

#define N_NODES 25000
#define N_EDGES 100000
#define NODE_IN 8
#define HID 32

// Scratch (device globals — allocation is forbidden). Device-side access only.
__device__ float g_h1[N_NODES * HID];
__device__ float g_h2[N_NODES * HID];
__device__ float g_agg[N_NODES * HID];
__device__ float g_cnt[N_NODES];
__device__ float g_inv[N_NODES];
__device__ int2  g_sd[N_EDGES];     // packed {src, dst}
__device__ int   g_bad64;

// ---------------------------------------------------------------------------
// Packed f32x2 helpers (Blackwell FFMA2 — only reachable via PTX)
// ---------------------------------------------------------------------------
__device__ __forceinline__ unsigned long long pk2(float lo, float hi) {
    unsigned long long r;
    asm("mov.b64 %0, {%1, %2};" : "=l"(r) : "f"(lo), "f"(hi));
    return r;
}
__device__ __forceinline__ void upk2(unsigned long long v, float& lo, float& hi) {
    asm("mov.b64 {%0, %1}, %2;" : "=f"(lo), "=f"(hi) : "l"(v));
}
__device__ __forceinline__ unsigned long long fma2(unsigned long long a,
                                                   unsigned long long b,
                                                   unsigned long long c) {
#if defined(__CUDA_ARCH__) && (__CUDA_ARCH__ >= 1000)
    unsigned long long d;
    asm("fma.rn.f32x2 %0, %1, %2, %3;" : "=l"(d) : "l"(a), "l"(b), "l"(c));
    return d;
#else
    float alo, ahi, blo, bhi, clo, chi;
    upk2(a, alo, ahi); upk2(b, blo, bhi); upk2(c, clo, chi);
    return pk2(fmaf(alo, blo, clo), fmaf(ahi, bhi, chi));
#endif
}

// ---------------------------------------------------------------------------
// zero_all: agg + cnt + flag, float4-vectorized (runs before detect)
// ---------------------------------------------------------------------------
__global__ void zero_all_kernel() {
    int i = blockIdx.x * blockDim.x + threadIdx.x;
    if (i < N_NODES * HID / 4) ((float4*)g_agg)[i] = make_float4(0.f, 0.f, 0.f, 0.f);
    if (i < N_NODES / 4)       ((float4*)g_cnt)[i] = make_float4(0.f, 0.f, 0.f, 0.f);
    if (i == 0) g_bad64 = 0;
}

__global__ void zero_agg_kernel() {
    int i = blockIdx.x * blockDim.x + threadIdx.x;
    if (i < N_NODES * HID / 4) ((float4*)g_agg)[i] = make_float4(0.f, 0.f, 0.f, 0.f);
}

// ---------------------------------------------------------------------------
// Detect int64 vs int32 edge_index. Reads the first N_EDGES words as int64
// (covers exactly the int32 buffer, or the src half of an int64 buffer — no
// OOB either way). int64 data -> all in [0,N_NODES) -> flag stays 0.
// Warp-ballot + plain store: NO contended atomics (same-value store races ok).
// ---------------------------------------------------------------------------
__global__ void idx_detect_kernel(const void* __restrict__ ei) {
    int e = blockIdx.x * blockDim.x + threadIdx.x;
    bool bad = false;
    if (e < N_EDGES) {
        long long v = ((const long long*)ei)[e];
        bad = (v < 0 || v >= N_NODES);
    }
    if (__any_sync(0xffffffffu, bad) && (threadIdx.x & 31u) == 0u && bad)
        g_bad64 = 1;
}

__global__ void idx_convert_kernel(const void* __restrict__ ei) {
    int e = blockIdx.x * blockDim.x + threadIdx.x;
    if (e >= N_EDGES) return;
    const bool is64 = (g_bad64 == 0);
    long long s, d;
    if (is64) {
        s = ((const long long*)ei)[e];
        d = ((const long long*)ei)[N_EDGES + e];
    } else {
        s = ((const int*)ei)[e];
        d = ((const int*)ei)[N_EDGES + e];
    }
    int si = (int)s, di = (int)d;
    si = si < 0 ? 0 : (si >= N_NODES ? N_NODES - 1 : si);
    di = di < 0 ? 0 : (di >= N_NODES ? N_NODES - 1 : di);
    g_sd[e] = make_int2(si, di);
}

// ---------------------------------------------------------------------------
// In-degree counts (dst is layer-invariant; runs once per replay)
// ---------------------------------------------------------------------------
__global__ void degree_kernel() {
    int e = blockIdx.x * blockDim.x + threadIdx.x;
    if (e < N_EDGES) atomicAdd(&g_cnt[g_sd[e].y], 1.0f);
}

// ---------------------------------------------------------------------------
// Edge kernel: one warp per edge (grid-stride), packed f32x2 math.
// lane o computes msg[o] = sum_i h[src,i] * relu( ea . W[:, i*32+o] + b )
// Two adjacent i-columns are processed together as an f32x2 pair; weights are
// pre-packed in smem as float2 so LDS.64 feeds fma.rn.f32x2 directly.
// SEL: 0 -> param x, 1 -> g_h1, 2 -> g_h2 (compile-time).
// ---------------------------------------------------------------------------
template <int IN, int SEL>
__global__ void __launch_bounds__(256)
edge_kernel(const float* __restrict__ x,
            const float* __restrict__ ea,
            const float* __restrict__ w_mlp,  // [4, IN*HID] row-major
            const float* __restrict__ b_mlp)  // [IN*HID]
{
    constexpr int COLS  = IN * HID;
    constexpr int PAIRS = IN / 2;
    // ws2[(p*4 + k)*HID + o] = { W[k][2p*HID+o], W[k][(2p+1)*HID+o] }
    __shared__ float2 ws2[PAIRS * 4 * HID];
    // bs2[p*HID + o] = { b[2p*HID+o], b[(2p+1)*HID+o] }
    __shared__ float2 bs2[PAIRS * HID];

    for (int idx = threadIdx.x; idx < PAIRS * 4 * HID; idx += blockDim.x) {
        int o = idx & (HID - 1);
        int k = (idx >> 5) & 3;
        int p = idx >> 7;
        ws2[idx] = make_float2(w_mlp[k * COLS + (2 * p) * HID + o],
                               w_mlp[k * COLS + (2 * p + 1) * HID + o]);
    }
    for (int idx = threadIdx.x; idx < PAIRS * HID; idx += blockDim.x) {
        int o = idx & (HID - 1);
        int p = idx >> 5;
        bs2[idx] = make_float2(b_mlp[(2 * p) * HID + o],
                               b_mlp[(2 * p + 1) * HID + o]);
    }
    __syncthreads();

    const int lane   = (int)(threadIdx.x & 31u);
    const int warp   = (int)((blockIdx.x * blockDim.x + threadIdx.x) >> 5);
    const int nwarps = (int)((gridDim.x * blockDim.x) >> 5);

    for (int e = warp; e < N_EDGES; e += nwarps) {
        const int2 sd = g_sd[e];
        const int src = sd.x;
        const int dst = sd.y;

        float xv;
        if (SEL == 0)      xv = x[src * IN + (lane & (IN - 1))];
        else if (SEL == 1) xv = g_h1[src * IN + (lane & (IN - 1))];
        else               xv = g_h2[src * IN + (lane & (IN - 1))];

        const float4 eav = *(const float4*)(ea + 4 * e);
        const unsigned long long ea0 = pk2(eav.x, eav.x);
        const unsigned long long ea1 = pk2(eav.y, eav.y);
        const unsigned long long ea2 = pk2(eav.z, eav.z);
        const unsigned long long ea3 = pk2(eav.w, eav.w);

        unsigned long long msg2 = pk2(0.0f, 0.0f);
        #pragma unroll
        for (int p = 0; p < PAIRS; ++p) {
            float xlo = __shfl_sync(0xffffffffu, xv, 2 * p);
            float xhi = __shfl_sync(0xffffffffu, xv, 2 * p + 1);

            float2 b2 = bs2[p * HID + lane];
            unsigned long long acc = pk2(b2.x, b2.y);
            int base = (p * 4) * HID + lane;
            float2 w0 = ws2[base];
            float2 w1 = ws2[base + HID];
            float2 w2 = ws2[base + 2 * HID];
            float2 w3 = ws2[base + 3 * HID];
            acc = fma2(ea0, pk2(w0.x, w0.y), acc);
            acc = fma2(ea1, pk2(w1.x, w1.y), acc);
            acc = fma2(ea2, pk2(w2.x, w2.y), acc);
            acc = fma2(ea3, pk2(w3.x, w3.y), acc);

            float alo, ahi;
            upk2(acc, alo, ahi);
            alo = fmaxf(alo, 0.0f);
            ahi = fmaxf(ahi, 0.0f);
            msg2 = fma2(pk2(xlo, xhi), pk2(alo, ahi), msg2);
        }
        float mlo, mhi;
        upk2(msg2, mlo, mhi);
        atomicAdd(&g_agg[dst * HID + lane], mlo + mhi);
    }
}

// ---------------------------------------------------------------------------
// Node update: h_out = relu(agg/max(cnt,1) + h_in @ root + bias)
// One warp per node; lane = output feature.
// SEL input: 0 -> x param, 1 -> g_h1. OUTSEL: 1 -> g_h1, 2 -> g_h2.
// ---------------------------------------------------------------------------
template <int IN, int SEL, int OUTSEL, bool FIRST>
__global__ void __launch_bounds__(256)
node_kernel(const float* __restrict__ x,
            const float* __restrict__ root,   // [IN, HID]
            const float* __restrict__ bias)   // [HID]
{
    __shared__ float rs[IN * HID];
    for (int i = threadIdx.x; i < IN * HID; i += blockDim.x) rs[i] = root[i];
    __syncthreads();

    const int lane = (int)(threadIdx.x & 31u);
    const int n    = (int)((blockIdx.x * blockDim.x + threadIdx.x) >> 5);
    if (n >= N_NODES) return;

    float inv;
    if (FIRST) {
        float c = g_cnt[n];
        inv = 1.0f / fmaxf(c, 1.0f);
        if (lane == 0) g_inv[n] = inv;
    } else {
        inv = g_inv[n];
    }

    float hv;
    if (SEL == 0) hv = x[n * IN + (lane & (IN - 1))];
    else          hv = g_h1[n * IN + (lane & (IN - 1))];

    float acc = g_agg[n * HID + lane] * inv + bias[lane];
    #pragma unroll
    for (int i = 0; i < IN; ++i)
        acc = fmaf(__shfl_sync(0xffffffffu, hv, i), rs[i * HID + lane], acc);

    float r = fmaxf(acc, 0.0f);
    if (OUTSEL == 1) g_h1[n * HID + lane] = r;
    else             g_h2[n * HID + lane] = r;
}

// ---------------------------------------------------------------------------
// Layer-3 node update fused with output head:
// h3 = relu(agg/cnt + h2 @ root3 + bias3)
// t  = relu(h3 @ w_out1 + b_out1); out = t @ w_out2 + b_out2
// ---------------------------------------------------------------------------
__global__ void __launch_bounds__(256)
node3_kernel(const float* __restrict__ root,    // [HID, HID]
             const float* __restrict__ bias,    // [HID]
             const float* __restrict__ w_out1,  // [HID, HID]
             const float* __restrict__ b_out1,  // [HID]
             const float* __restrict__ w_out2,  // [HID, 1]
             const float* __restrict__ b_out2,  // [1]
             float* __restrict__ out)
{
    __shared__ float rs[HID * HID];
    __shared__ float wo[HID * HID];
    for (int i = threadIdx.x; i < HID * HID; i += blockDim.x) {
        rs[i] = root[i];
        wo[i] = w_out1[i];
    }
    __syncthreads();

    const int lane = (int)(threadIdx.x & 31u);
    const int n    = (int)((blockIdx.x * blockDim.x + threadIdx.x) >> 5);
    if (n >= N_NODES) return;

    float inv = g_inv[n];
    float acc = g_agg[n * HID + lane] * inv + bias[lane];
    float hv  = g_h2[n * HID + lane];
    #pragma unroll
    for (int i = 0; i < HID; ++i)
        acc = fmaf(__shfl_sync(0xffffffffu, hv, i), rs[i * HID + lane], acc);
    float h3 = fmaxf(acc, 0.0f);

    float acc2 = b_out1[lane];
    #pragma unroll
    for (int o = 0; o < HID; ++o)
        acc2 = fmaf(__shfl_sync(0xffffffffu, h3, o), wo[o * HID + lane], acc2);

    float t = fmaxf(acc2, 0.0f) * w_out2[lane];
    #pragma unroll
    for (int off = 16; off; off >>= 1)
        t += __shfl_xor_sync(0xffffffffu, t, off);

    if (lane == 0) out[n] = t + b_out2[0];
}

// ---------------------------------------------------------------------------
extern "C" void kernel_launch(void* const* d_in, const int* in_sizes, int n_in,
                              void* d_out, int out_size)
{
    (void)in_sizes; (void)n_in; (void)out_size;

    const float* x      = (const float*)d_in[0];
    const void*  ei     = d_in[1];                 // dtype detected on device
    const float* ea     = (const float*)d_in[2];
    const float* w_mlp1 = (const float*)d_in[3];
    const float* b_mlp1 = (const float*)d_in[4];
    const float* root1  = (const float*)d_in[5];
    const float* bias1  = (const float*)d_in[6];
    const float* w_mlp2 = (const float*)d_in[7];
    const float* b_mlp2 = (const float*)d_in[8];
    const float* root2  = (const float*)d_in[9];
    const float* bias2  = (const float*)d_in[10];
    const float* w_mlp3 = (const float*)d_in[11];
    const float* b_mlp3 = (const float*)d_in[12];
    const float* root3  = (const float*)d_in[13];
    const float* bias3  = (const float*)d_in[14];
    const float* w_out1 = (const float*)d_in[15];
    const float* b_out1 = (const float*)d_in[16];
    const float* w_out2 = (const float*)d_in[17];
    const float* b_out2 = (const float*)d_in[18];
    float*       out    = (float*)d_out;

    const int Z4 = (N_NODES * HID / 4 + 255) / 256;  // float4 zero blocks
    const int DB = (N_EDGES + 255) / 256;            // per-edge blocks
    const int NB = (N_NODES * 32 + 255) / 256;       // node blocks (warp/node)
    const int EB = 1184;                             // edge blocks: 8/SM x 148 SM

    // Prologue: zero everything, detect index dtype, convert+clamp, degrees
    zero_all_kernel<<<Z4, 256>>>();
    idx_detect_kernel<<<DB, 256>>>(ei);
    idx_convert_kernel<<<DB, 256>>>(ei);
    degree_kernel<<<DB, 256>>>();

    // Layer 1 (IN = 8): x -> g_h1
    edge_kernel<NODE_IN, 0><<<EB, 256>>>(x, ea, w_mlp1, b_mlp1);
    node_kernel<NODE_IN, 0, 1, true><<<NB, 256>>>(x, root1, bias1);

    // Layer 2 (IN = 32): g_h1 -> g_h2
    zero_agg_kernel<<<Z4, 256>>>();
    edge_kernel<HID, 1><<<EB, 256>>>(x, ea, w_mlp2, b_mlp2);
    node_kernel<HID, 1, 2, false><<<NB, 256>>>(x, root2, bias2);

    // Layer 3 (IN = 32) + fused output head: g_h2 -> out
    zero_agg_kernel<<<Z4, 256>>>();
    edge_kernel<HID, 2><<<EB, 256>>>(x, ea, w_mlp3, b_mlp3);
    node3_kernel<<<NB, 256>>>(root3, bias3, w_out1, b_out1, w_out2, b_out2, out);
}

// round 7
// speedup vs baseline: 1.8062x; 1.7658x over previous
#include <cuda_runtime.h>

#define N_NODES 25000
#define N_EDGES 100000
#define NODE_IN 8
#define HID 32

// Scratch (device globals — allocation is forbidden). Device-side access only.
__device__ float g_h1[N_NODES * HID];
__device__ float g_h2[N_NODES * HID];
__device__ float g_agg[N_NODES * HID];
__device__ float g_cnt[N_NODES];
__device__ float g_inv[N_NODES];
__device__ int2  g_sd[N_EDGES];     // packed {src, dst}
__device__ int   g_bad64 = 0;       // raised (never lowered) if edge_index is int32

// ---------------------------------------------------------------------------
// Packed f32x2 helpers (Blackwell FFMA2 — only reachable via PTX)
// ---------------------------------------------------------------------------
__device__ __forceinline__ unsigned long long pk2(float lo, float hi) {
    unsigned long long r;
    asm("mov.b64 %0, {%1, %2};" : "=l"(r) : "f"(lo), "f"(hi));
    return r;
}
__device__ __forceinline__ void upk2(unsigned long long v, float& lo, float& hi) {
    asm("mov.b64 {%0, %1}, %2;" : "=f"(lo), "=f"(hi) : "l"(v));
}
__device__ __forceinline__ unsigned long long fma2(unsigned long long a,
                                                   unsigned long long b,
                                                   unsigned long long c) {
    unsigned long long d;
    asm("fma.rn.f32x2 %0, %1, %2, %3;" : "=l"(d) : "l"(a), "l"(b), "l"(c));
    return d;
}

// ---------------------------------------------------------------------------
// Prologue: zero agg + cnt (float4) and detect index dtype, all in one kernel.
// Reads the first N_EDGES words as int64: spans exactly the int32 buffer, or
// the src half of an int64 buffer — no OOB either way. int64 data keeps the
// flag 0; int32 data raises it (same-value store races are benign; the flag
// is never lowered, so behavior is identical on every call).
// ---------------------------------------------------------------------------
__global__ void prologue_kernel(const void* __restrict__ ei) {
    int i = blockIdx.x * blockDim.x + threadIdx.x;
    const float4 z4 = make_float4(0.f, 0.f, 0.f, 0.f);
    if (i < N_NODES * HID / 4) ((float4*)g_agg)[i] = z4;
    if (i < N_NODES / 4)       ((float4*)g_cnt)[i] = z4;
    if (i < N_EDGES) {
        long long v = ((const long long*)ei)[i];
        if (v < 0 || v >= N_NODES) g_bad64 = 1;
    }
}

// ---------------------------------------------------------------------------
// Convert indices (dtype per flag, clamped) + accumulate in-degrees.
// ---------------------------------------------------------------------------
__global__ void convert_degree_kernel(const void* __restrict__ ei) {
    int e = blockIdx.x * blockDim.x + threadIdx.x;
    if (e >= N_EDGES) return;
    const bool is64 = (g_bad64 == 0);
    long long s, d;
    if (is64) {
        s = ((const long long*)ei)[e];
        d = ((const long long*)ei)[N_EDGES + e];
    } else {
        s = ((const int*)ei)[e];
        d = ((const int*)ei)[N_EDGES + e];
    }
    int si = (int)s, di = (int)d;
    si = si < 0 ? 0 : (si >= N_NODES ? N_NODES - 1 : si);
    di = di < 0 ? 0 : (di >= N_NODES ? N_NODES - 1 : di);
    g_sd[e] = make_int2(si, di);
    atomicAdd(&g_cnt[di], 1.0f);
}

// ---------------------------------------------------------------------------
// Edge kernel: one warp per GROUP of ET=4 edges (grid-stride).
// lane o computes msg[o] = sum_i h[src,i] * relu( ea . W[:, i*32+o] + b )
// Weights live in smem as packed f32x2 (ULL) over adjacent i-columns; each
// weight load is reused across ET edges -> LDS traffic / 4 vs round 6.
// SEL: 0 -> param x, 1 -> g_h1, 2 -> g_h2 (compile-time).
// ---------------------------------------------------------------------------
template <int IN, int SEL>
__global__ void __launch_bounds__(256, 2)
edge_kernel(const float* __restrict__ x,
            const float* __restrict__ ea,
            const float* __restrict__ w_mlp,  // [4, IN*HID] row-major
            const float* __restrict__ b_mlp)  // [IN*HID]
{
    constexpr int COLS  = IN * HID;
    constexpr int PAIRS = IN / 2;
    constexpr int ET    = 4;
    // ws2[(p*4+k)*HID + o] = pack( W[k][2p*HID+o], W[k][(2p+1)*HID+o] )
    __shared__ unsigned long long ws2[PAIRS * 4 * HID];
    __shared__ unsigned long long bs2[PAIRS * HID];

    for (int idx = threadIdx.x; idx < PAIRS * 4 * HID; idx += blockDim.x) {
        int o = idx & (HID - 1);
        int k = (idx >> 5) & 3;
        int p = idx >> 7;
        ws2[idx] = pk2(w_mlp[k * COLS + (2 * p) * HID + o],
                       w_mlp[k * COLS + (2 * p + 1) * HID + o]);
    }
    for (int idx = threadIdx.x; idx < PAIRS * HID; idx += blockDim.x) {
        int o = idx & (HID - 1);
        int p = idx >> 5;
        bs2[idx] = pk2(b_mlp[(2 * p) * HID + o], b_mlp[(2 * p + 1) * HID + o]);
    }
    __syncthreads();

    const int lane   = (int)(threadIdx.x & 31u);
    const int warp   = (int)((blockIdx.x * blockDim.x + threadIdx.x) >> 5);
    const int nwarps = (int)((gridDim.x * blockDim.x) >> 5);
    const int ngroups = (N_EDGES + ET - 1) / ET;

    for (int g = warp; g < ngroups; g += nwarps) {
        const int e0 = g * ET;

        int2  sd[ET];
        float xv[ET];
        unsigned long long eap[ET][4];
        #pragma unroll
        for (int j = 0; j < ET; ++j) {
            int e = e0 + j;
            e = e < N_EDGES ? e : N_EDGES - 1;   // clamp loads; atomic is guarded
            sd[j] = g_sd[e];
            float4 v = *(const float4*)(ea + 4 * e);
            eap[j][0] = pk2(v.x, v.x);
            eap[j][1] = pk2(v.y, v.y);
            eap[j][2] = pk2(v.z, v.z);
            eap[j][3] = pk2(v.w, v.w);
            if (SEL == 0)      xv[j] = x[sd[j].x * IN + (lane & (IN - 1))];
            else if (SEL == 1) xv[j] = g_h1[sd[j].x * IN + (lane & (IN - 1))];
            else               xv[j] = g_h2[sd[j].x * IN + (lane & (IN - 1))];
        }

        unsigned long long msg2[ET];
        #pragma unroll
        for (int j = 0; j < ET; ++j) msg2[j] = 0ull;   // bits(0,0) == (0.f,0.f)

        #pragma unroll
        for (int p = 0; p < PAIRS; ++p) {
            const unsigned long long b2 = bs2[p * HID + lane];
            const int base = (p * 4) * HID + lane;
            const unsigned long long w0 = ws2[base];
            const unsigned long long w1 = ws2[base + HID];
            const unsigned long long w2 = ws2[base + 2 * HID];
            const unsigned long long w3 = ws2[base + 3 * HID];
            #pragma unroll
            for (int j = 0; j < ET; ++j) {
                float xlo = __shfl_sync(0xffffffffu, xv[j], 2 * p);
                float xhi = __shfl_sync(0xffffffffu, xv[j], 2 * p + 1);
                unsigned long long acc = fma2(eap[j][0], w0, b2);
                acc = fma2(eap[j][1], w1, acc);
                acc = fma2(eap[j][2], w2, acc);
                acc = fma2(eap[j][3], w3, acc);
                float alo, ahi;
                upk2(acc, alo, ahi);
                msg2[j] = fma2(pk2(xlo, xhi),
                               pk2(fmaxf(alo, 0.0f), fmaxf(ahi, 0.0f)),
                               msg2[j]);
            }
        }

        #pragma unroll
        for (int j = 0; j < ET; ++j) {
            float mlo, mhi;
            upk2(msg2[j], mlo, mhi);
            if (e0 + j < N_EDGES)
                atomicAdd(&g_agg[sd[j].y * HID + lane], mlo + mhi);
        }
    }
}

// ---------------------------------------------------------------------------
// Node update: h_out = relu(agg/max(cnt,1) + h_in @ root + bias)
// One warp per node; lane = output feature. Re-zeros its agg slot so the next
// layer's edge kernel (and next replay via prologue) sees zeros.
// SEL input: 0 -> x param, 1 -> g_h1. OUTSEL: 1 -> g_h1, 2 -> g_h2.
// ---------------------------------------------------------------------------
template <int IN, int SEL, int OUTSEL, bool FIRST>
__global__ void __launch_bounds__(256)
node_kernel(const float* __restrict__ x,
            const float* __restrict__ root,   // [IN, HID]
            const float* __restrict__ bias)   // [HID]
{
    __shared__ float rs[IN * HID];
    for (int i = threadIdx.x; i < IN * HID; i += blockDim.x) rs[i] = root[i];
    __syncthreads();

    const int lane = (int)(threadIdx.x & 31u);
    const int n    = (int)((blockIdx.x * blockDim.x + threadIdx.x) >> 5);
    if (n >= N_NODES) return;

    float inv;
    if (FIRST) {
        float c = g_cnt[n];
        inv = 1.0f / fmaxf(c, 1.0f);
        if (lane == 0) g_inv[n] = inv;
    } else {
        inv = g_inv[n];
    }

    float hv;
    if (SEL == 0) hv = x[n * IN + (lane & (IN - 1))];
    else          hv = g_h1[n * IN + (lane & (IN - 1))];

    float acc = g_agg[n * HID + lane] * inv + bias[lane];
    g_agg[n * HID + lane] = 0.0f;   // re-zero for the next layer
    #pragma unroll
    for (int i = 0; i < IN; ++i)
        acc = fmaf(__shfl_sync(0xffffffffu, hv, i), rs[i * HID + lane], acc);

    float r = fmaxf(acc, 0.0f);
    if (OUTSEL == 1) g_h1[n * HID + lane] = r;
    else             g_h2[n * HID + lane] = r;
}

// ---------------------------------------------------------------------------
// Layer-3 node update fused with output head:
// h3 = relu(agg/cnt + h2 @ root3 + bias3)
// t  = relu(h3 @ w_out1 + b_out1); out = t @ w_out2 + b_out2
// (agg left dirty; prologue re-zeros at the start of every call.)
// ---------------------------------------------------------------------------
__global__ void __launch_bounds__(256)
node3_kernel(const float* __restrict__ root,    // [HID, HID]
             const float* __restrict__ bias,    // [HID]
             const float* __restrict__ w_out1,  // [HID, HID]
             const float* __restrict__ b_out1,  // [HID]
             const float* __restrict__ w_out2,  // [HID, 1]
             const float* __restrict__ b_out2,  // [1]
             float* __restrict__ out)
{
    __shared__ float rs[HID * HID];
    __shared__ float wo[HID * HID];
    for (int i = threadIdx.x; i < HID * HID; i += blockDim.x) {
        rs[i] = root[i];
        wo[i] = w_out1[i];
    }
    __syncthreads();

    const int lane = (int)(threadIdx.x & 31u);
    const int n    = (int)((blockIdx.x * blockDim.x + threadIdx.x) >> 5);
    if (n >= N_NODES) return;

    float inv = g_inv[n];
    float acc = g_agg[n * HID + lane] * inv + bias[lane];
    float hv  = g_h2[n * HID + lane];
    #pragma unroll
    for (int i = 0; i < HID; ++i)
        acc = fmaf(__shfl_sync(0xffffffffu, hv, i), rs[i * HID + lane], acc);
    float h3 = fmaxf(acc, 0.0f);

    float acc2 = b_out1[lane];
    #pragma unroll
    for (int o = 0; o < HID; ++o)
        acc2 = fmaf(__shfl_sync(0xffffffffu, h3, o), wo[o * HID + lane], acc2);

    float t = fmaxf(acc2, 0.0f) * w_out2[lane];
    #pragma unroll
    for (int off = 16; off; off >>= 1)
        t += __shfl_xor_sync(0xffffffffu, t, off);

    if (lane == 0) out[n] = t + b_out2[0];
}

// ---------------------------------------------------------------------------
extern "C" void kernel_launch(void* const* d_in, const int* in_sizes, int n_in,
                              void* d_out, int out_size)
{
    (void)in_sizes; (void)n_in; (void)out_size;

    const float* x      = (const float*)d_in[0];
    const void*  ei     = d_in[1];                 // dtype detected on device
    const float* ea     = (const float*)d_in[2];
    const float* w_mlp1 = (const float*)d_in[3];
    const float* b_mlp1 = (const float*)d_in[4];
    const float* root1  = (const float*)d_in[5];
    const float* bias1  = (const float*)d_in[6];
    const float* w_mlp2 = (const float*)d_in[7];
    const float* b_mlp2 = (const float*)d_in[8];
    const float* root2  = (const float*)d_in[9];
    const float* bias2  = (const float*)d_in[10];
    const float* w_mlp3 = (const float*)d_in[11];
    const float* b_mlp3 = (const float*)d_in[12];
    const float* root3  = (const float*)d_in[13];
    const float* bias3  = (const float*)d_in[14];
    const float* w_out1 = (const float*)d_in[15];
    const float* b_out1 = (const float*)d_in[16];
    const float* w_out2 = (const float*)d_in[17];
    const float* b_out2 = (const float*)d_in[18];
    float*       out    = (float*)d_out;

    const int PB = (N_NODES * HID / 4 + 255) / 256;  // prologue blocks (covers all ranges)
    const int DB = (N_EDGES + 255) / 256;            // per-edge blocks
    const int NB = (N_NODES * 32 + 255) / 256;       // node blocks (warp/node)
    const int EB = 592;                              // edge blocks (grid-stride groups)

    prologue_kernel<<<PB, 256>>>(ei);
    convert_degree_kernel<<<DB, 256>>>(ei);

    // Layer 1 (IN = 8): x -> g_h1
    edge_kernel<NODE_IN, 0><<<EB, 256>>>(x, ea, w_mlp1, b_mlp1);
    node_kernel<NODE_IN, 0, 1, true><<<NB, 256>>>(x, root1, bias1);

    // Layer 2 (IN = 32): g_h1 -> g_h2
    edge_kernel<HID, 1><<<EB, 256>>>(x, ea, w_mlp2, b_mlp2);
    node_kernel<HID, 1, 2, false><<<NB, 256>>>(x, root2, bias2);

    // Layer 3 (IN = 32) + fused output head: g_h2 -> out
    edge_kernel<HID, 2><<<EB, 256>>>(x, ea, w_mlp3, b_mlp3);
    node3_kernel<<<NB, 256>>>(root3, bias3, w_out1, b_out1, w_out2, b_out2, out);
}